// round 1
// baseline (speedup 1.0000x reference)
#include <cuda_runtime.h>
#include <string.h>

#define BB 8
#define TT 8192
#define SN 8192
#define FF 64
#define DD 64
#define MMF 128
#define TWOM 256
#define DV 65
#define EPSF 1e-9f
#define SCALEF 0.0625f   /* 1/sqrt(2*128) = 1/16 */

#define XPAD 65     /* x tile row stride (odd -> conflict-free with rows rg+16k) */
#define VPAD 68     /* v tile row stride (float4 aligned) */
#define KPPAD 257   /* phi tile row stride */
#define KVPAD 68    /* kv smem row stride (float4/float2 aligned) */

#define NCHUNK 16   /* S-chunks per batch in kv kernel */

// Deterministic two-stage reduction scratch (no device-side malloc allowed).
__device__ float g_part[BB * NCHUNK * TWOM * DV];   // ~8.5 MB
__device__ float g_kv[BB * TWOM * DV];

// Packed f32x2 FMA (2 fp32 FMAs per instruction; ptxas won't auto-fuse).
static __device__ __forceinline__ float2 ffma2(float2 a, float2 b, float2 c) {
    unsigned long long au, bu, cu, du;
    memcpy(&au, &a, 8); memcpy(&bu, &b, 8); memcpy(&cu, &c, 8);
    asm("fma.rn.f32x2 %0, %1, %2, %3;" : "=l"(du) : "l"(au), "l"(bu), "l"(cu));
    float2 d; memcpy(&d, &du, 8);
    return d;
}

// ---------------------------------------------------------------------------
// Kernel 1: per (b, chunk) block, 512 rows of S in 8 tiles of 64.
// Computes phi(key) tile in SMEM, accumulates kv partial in registers,
// writes partial to g_part. 256 threads.
// ---------------------------------------------------------------------------
__global__ __launch_bounds__(256, 1)
void kv_kernel(const float* __restrict__ key,
               const float* __restrict__ value,
               const float* __restrict__ omega) {
    extern __shared__ float sm[];
    float* omega_s = sm;                        // [f][m]   64*128
    float* x_s     = omega_s + FF * MMF;        // [64][XPAD]
    float* v_s     = x_s + 64 * XPAD;           // [64][VPAD] (col 64 = 1.0)
    float* kphi_s  = v_s + 64 * VPAD;           // [64][KPPAD]
    float* ssq_s   = kphi_s + 64 * KPPAD;       // [64]

    const int tid = threadIdx.x;
    const int b = blockIdx.y;
    const int chunk = blockIdx.x;
    const int rg = tid & 15;
    const int mg = tid >> 4;

    // Load omega transposed into SMEM: omega_s[f*128 + m]
    for (int idx = tid; idx < MMF * FF; idx += 256) {
        int m = idx >> 6, f = idx & 63;
        omega_s[f * MMF + m] = omega[idx];
    }

    float2 acc2[32];
#pragma unroll
    for (int p = 0; p < 32; ++p) acc2[p] = make_float2(0.f, 0.f);
    float acc64 = 0.f;

    for (int tile = 0; tile < 8; ++tile) {
        const int s0 = chunk * 512 + tile * 64;
        __syncthreads();  // previous tile fully consumed

        const float4* kp = (const float4*)(key   + ((size_t)b * SN + s0) * FF);
        const float4* vp = (const float4*)(value + ((size_t)b * SN + s0) * FF);
#pragma unroll
        for (int q = 0; q < 4; ++q) {
            int idx = tid + q * 256;
            int r = idx >> 4, c = (idx & 15) * 4;
            float4 xv = kp[idx];
            float* xd = &x_s[r * XPAD + c];
            xd[0] = xv.x; xd[1] = xv.y; xd[2] = xv.z; xd[3] = xv.w;
            *(float4*)&v_s[r * VPAD + c] = vp[idx];
        }
        if (tid < 64) {
            v_s[tid * VPAD + 64] = 1.0f;
            v_s[tid * VPAD + 65] = 0.f;
            v_s[tid * VPAD + 66] = 0.f;
            v_s[tid * VPAD + 67] = 0.f;
        }
        __syncthreads();

        if (tid < 64) {
            float ss = 0.f;
#pragma unroll
            for (int f = 0; f < FF; ++f) {
                float xv = x_s[tid * XPAD + f];
                ss = fmaf(xv, xv, ss);
            }
            ssq_s[tid] = 0.5f * ss;
        }
        __syncthreads();

        // xw: thread owns rows {rg+16k} x m-pairs {2mg+32i, +1}
        float2 xw[4][4];
#pragma unroll
        for (int k = 0; k < 4; ++k)
#pragma unroll
            for (int i = 0; i < 4; ++i) xw[k][i] = make_float2(0.f, 0.f);

#pragma unroll 2
        for (int f = 0; f < FF; ++f) {
            float xv[4];
#pragma unroll
            for (int k = 0; k < 4; ++k) xv[k] = x_s[(rg + 16 * k) * XPAD + f];
            const float2* om2 = (const float2*)&omega_s[f * MMF];
            float2 ov[4];
#pragma unroll
            for (int i = 0; i < 4; ++i) ov[i] = om2[mg + 16 * i];
#pragma unroll
            for (int k = 0; k < 4; ++k) {
                float2 xk = make_float2(xv[k], xv[k]);
#pragma unroll
                for (int i = 0; i < 4; ++i) xw[k][i] = ffma2(xk, ov[i], xw[k][i]);
            }
        }

        // phi features -> kphi_s
#pragma unroll
        for (int k = 0; k < 4; ++k) {
            int r = rg + 16 * k;
            float sc = ssq_s[r];
            float* kr = &kphi_s[r * KPPAD];
#pragma unroll
            for (int i = 0; i < 4; ++i) {
                int m = 2 * mg + 32 * i;
                float w0 = xw[k][i].x, w1 = xw[k][i].y;
                kr[m]           = (__expf(w0 - sc) + EPSF) * SCALEF;
                kr[m + 1]       = (__expf(w1 - sc) + EPSF) * SCALEF;
                kr[m + MMF]     = (__expf(-w0 - sc) + EPSF) * SCALEF;
                kr[m + MMF + 1] = (__expf(-w1 - sc) + EPSF) * SCALEF;
            }
        }
        __syncthreads();

        // kv accumulate: thread owns feature j = tid, all 65 d-cols.
#pragma unroll 2
        for (int r = 0; r < 64; ++r) {
            float kk = kphi_s[r * KPPAD + tid];
            float2 kk2 = make_float2(kk, kk);
            const float2* vr = (const float2*)&v_s[r * VPAD];
#pragma unroll
            for (int p = 0; p < 32; ++p) acc2[p] = ffma2(kk2, vr[p], acc2[p]);
            acc64 = fmaf(kk, v_s[r * VPAD + 64], acc64);
        }
    }

    float* dst = &g_part[(((size_t)b * NCHUNK + chunk) * TWOM + tid) * DV];
#pragma unroll
    for (int p = 0; p < 32; ++p) {
        dst[2 * p]     = acc2[p].x;
        dst[2 * p + 1] = acc2[p].y;
    }
    dst[64] = acc64;
}

// ---------------------------------------------------------------------------
// Kernel 2: deterministic reduction of the NCHUNK partials into g_kv.
// ---------------------------------------------------------------------------
__global__ void reduce_kernel() {
    int idx = blockIdx.x * blockDim.x + threadIdx.x;
    if (idx < BB * TWOM * DV) {
        int b = idx / (TWOM * DV);
        int rem = idx - b * (TWOM * DV);
        float s = 0.f;
#pragma unroll
        for (int c = 0; c < NCHUNK; ++c)
            s += g_part[((size_t)b * NCHUNK + c) * (TWOM * DV) + rem];
        g_kv[idx] = s;
    }
}

// ---------------------------------------------------------------------------
// Kernel 3: per (b, t-tile of 64) block: phi(query) tile + qkv GEMM + normalize.
// ---------------------------------------------------------------------------
__global__ __launch_bounds__(256, 1)
void qkv_kernel(const float* __restrict__ query,
                const float* __restrict__ omega,
                float* __restrict__ out) {
    extern __shared__ float sm[];
    float* omega_s = sm;                        // 64*128
    float* kv_s    = omega_s + FF * MMF;        // [256][KVPAD]
    float* x_s     = kv_s + TWOM * KVPAD;       // [64][XPAD]
    float* qphi_s  = x_s + 64 * XPAD;           // [64][KPPAD]
    float* ssq_s   = qphi_s + 64 * KPPAD;       // [64]
    float* norm_s  = ssq_s + 64;                // [64]

    const int tid = threadIdx.x;
    const int b = blockIdx.y;
    const int t0 = blockIdx.x * 64;
    const int rg = tid & 15;
    const int mg = tid >> 4;

    for (int idx = tid; idx < MMF * FF; idx += 256) {
        int m = idx >> 6, f = idx & 63;
        omega_s[f * MMF + m] = omega[idx];
    }
    const float* kvsrc = &g_kv[(size_t)b * TWOM * DV];
    for (int idx = tid; idx < TWOM * DV; idx += 256) {
        int j = idx / DV, d = idx - j * DV;
        kv_s[j * KVPAD + d] = kvsrc[idx];
    }
    const float4* qp = (const float4*)(query + ((size_t)b * TT + t0) * FF);
#pragma unroll
    for (int q = 0; q < 4; ++q) {
        int idx = tid + q * 256;
        int r = idx >> 4, c = (idx & 15) * 4;
        float4 xv = qp[idx];
        float* xd = &x_s[r * XPAD + c];
        xd[0] = xv.x; xd[1] = xv.y; xd[2] = xv.z; xd[3] = xv.w;
    }
    __syncthreads();

    if (tid < 64) {
        float ss = 0.f;
#pragma unroll
        for (int f = 0; f < FF; ++f) {
            float xv = x_s[tid * XPAD + f];
            ss = fmaf(xv, xv, ss);
        }
        ssq_s[tid] = 0.5f * ss;
    }
    __syncthreads();

    float2 xw[4][4];
#pragma unroll
    for (int k = 0; k < 4; ++k)
#pragma unroll
        for (int i = 0; i < 4; ++i) xw[k][i] = make_float2(0.f, 0.f);

#pragma unroll 2
    for (int f = 0; f < FF; ++f) {
        float xv[4];
#pragma unroll
        for (int k = 0; k < 4; ++k) xv[k] = x_s[(rg + 16 * k) * XPAD + f];
        const float2* om2 = (const float2*)&omega_s[f * MMF];
        float2 ov[4];
#pragma unroll
        for (int i = 0; i < 4; ++i) ov[i] = om2[mg + 16 * i];
#pragma unroll
        for (int k = 0; k < 4; ++k) {
            float2 xk = make_float2(xv[k], xv[k]);
#pragma unroll
            for (int i = 0; i < 4; ++i) xw[k][i] = ffma2(xk, ov[i], xw[k][i]);
        }
    }

#pragma unroll
    for (int k = 0; k < 4; ++k) {
        int r = rg + 16 * k;
        float sc = ssq_s[r];
        float* qr = &qphi_s[r * KPPAD];
#pragma unroll
        for (int i = 0; i < 4; ++i) {
            int m = 2 * mg + 32 * i;
            float w0 = xw[k][i].x, w1 = xw[k][i].y;
            qr[m]           = (__expf(w0 - sc) + EPSF) * SCALEF;
            qr[m + 1]       = (__expf(w1 - sc) + EPSF) * SCALEF;
            qr[m + MMF]     = (__expf(-w0 - sc) + EPSF) * SCALEF;
            qr[m + MMF + 1] = (__expf(-w1 - sc) + EPSF) * SCALEF;
        }
    }
    __syncthreads();

    // qkv: thread = (row r, d-group dg of 16 cols). dg uniform per warp.
    const int r = tid & 63;
    const int dg = tid >> 6;
    float2 acc[8];
#pragma unroll
    for (int p = 0; p < 8; ++p) acc[p] = make_float2(0.f, 0.f);
    float accn = 0.f;

    const float* qr = &qphi_s[r * KPPAD];
#pragma unroll 2
    for (int m = 0; m < TWOM; ++m) {
        float qv = qr[m];
        float2 q2 = make_float2(qv, qv);
        const float2* kr = (const float2*)&kv_s[m * KVPAD + dg * 16];
#pragma unroll
        for (int p = 0; p < 8; ++p) acc[p] = ffma2(q2, kr[p], acc[p]);
        if (dg == 0) accn = fmaf(qv, kv_s[m * KVPAD + 64], accn);
    }
    if (dg == 0) norm_s[r] = accn;
    __syncthreads();

    float inv = 1.0f / norm_s[r];
    float2* o = (float2*)(out + ((size_t)b * TT + t0 + r) * DD + dg * 16);
#pragma unroll
    for (int p = 0; p < 8; ++p)
        o[p] = make_float2(acc[p].x * inv, acc[p].y * inv);
}

// ---------------------------------------------------------------------------

#define KV_SMEM  ((FF*MMF + 64*XPAD + 64*VPAD + 64*KPPAD + 64) * 4)
#define QKV_SMEM ((FF*MMF + TWOM*KVPAD + 64*XPAD + 64*KPPAD + 64 + 64) * 4)

extern "C" void kernel_launch(void* const* d_in, const int* in_sizes, int n_in,
                              void* d_out, int out_size) {
    // metadata order: query, value, key, omega
    const float* query = (const float*)d_in[0];
    const float* value = (const float*)d_in[1];
    const float* key   = (const float*)d_in[2];
    const float* omega = (const float*)d_in[3];
    float* out = (float*)d_out;

    cudaFuncSetAttribute(kv_kernel, cudaFuncAttributeMaxDynamicSharedMemorySize, KV_SMEM);
    cudaFuncSetAttribute(qkv_kernel, cudaFuncAttributeMaxDynamicSharedMemorySize, QKV_SMEM);

    kv_kernel<<<dim3(NCHUNK, BB), 256, KV_SMEM>>>(key, value, omega);
    reduce_kernel<<<(BB * TWOM * DV + 255) / 256, 256>>>();
    qkv_kernel<<<dim3(TT / 64, BB), 256, QKV_SMEM>>>(query, omega, out);
}

// round 3
// speedup vs baseline: 1.3753x; 1.3753x over previous
#include <cuda_runtime.h>
#include <string.h>

#define BB 8
#define TT 8192
#define SN 8192
#define FF 64
#define DD 64
#define MMF 128
#define TWOM 256
#define EPSF 1e-9f
#define SCALEF 0.0625f   /* 1/sqrt(2*128) */

#define NCHUNK 32
#define XP 66      /* x tile row stride */
#define VP 68      /* v tile row stride */
#define KPP 258    /* phi tile row stride */
#define KVW 66     /* kv row stride (col 64 = normalizer, 65 pad) */

__device__ float g_part[(size_t)BB * NCHUNK * TWOM * KVW];   // ~17.3 MB
__device__ float g_kv[BB * TWOM * KVW];

static __device__ __forceinline__ float2 ffma2(float2 a, float2 b, float2 c) {
    unsigned long long au, bu, cu, du;
    memcpy(&au, &a, 8); memcpy(&bu, &b, 8); memcpy(&cu, &c, 8);
    asm("fma.rn.f32x2 %0, %1, %2, %3;" : "=l"(du) : "l"(au), "l"(bu), "l"(cu));
    float2 d; memcpy(&d, &du, 8);
    return d;
}

// ---------------------------------------------------------------------------
// Kernel 1: block = (b, chunk of 256 s-rows in 4 tiles of 64). 512 threads.
// phi(key) tile in SMEM -> kv partial in registers -> g_part.
// ---------------------------------------------------------------------------
__global__ __launch_bounds__(512, 1)
void kv_kernel(const float* __restrict__ key,
               const float* __restrict__ value,
               const float* __restrict__ omega) {
    extern __shared__ float sm[];
    float* omega_s = sm;                 // [f][m] 64*128 = 8192
    float* x_s     = sm + 8192;          // [64][XP]  4224
    float* v_s     = x_s + 64 * XP;      // [64][VP]  4352
    float* kphi    = v_s + 64 * VP;      // [64][KPP] 16512

    const int tid = threadIdx.x;
    const int b = blockIdx.y;
    const int chunk = blockIdx.x;

    for (int idx = tid; idx < MMF * FF; idx += 512) {
        int m = idx >> 6, f = idx & 63;
        omega_s[f * MMF + m] = omega[idx];
    }

    const int rg = tid & 15;           // phi: rows rg+16k (k<4)
    const int mg = (tid >> 4) & 31;    // phi: pairs mg+32i (i<2) -> 64 pairs total
    const int fg = tid & 63;           // acc: features 2fg, 2fg+1, +128, +129
    const int dgrp = tid >> 6;         // acc: cols 8*dgrp..+7

    float2 acc[4][4];
#pragma unroll
    for (int j = 0; j < 4; ++j)
#pragma unroll
        for (int p = 0; p < 4; ++p) acc[j][p] = make_float2(0.f, 0.f);
    float accn[4] = {0.f, 0.f, 0.f, 0.f};

    for (int tile = 0; tile < 4; ++tile) {
        const int s0 = chunk * 256 + tile * 64;
        __syncthreads();   // previous tile fully consumed

        const float4* kp = (const float4*)(key   + ((size_t)b * SN + s0) * FF);
        const float4* vp = (const float4*)(value + ((size_t)b * SN + s0) * FF);
#pragma unroll
        for (int q = 0; q < 2; ++q) {
            int idx = tid + q * 512;
            int r = idx >> 4, c = (idx & 15) * 4;
            float4 xv = kp[idx];
            float* xd = &x_s[r * XP + c];
            *(float2*)xd       = make_float2(xv.x, xv.y);
            *(float2*)(xd + 2) = make_float2(xv.z, xv.w);
            *(float4*)&v_s[r * VP + c] = vp[idx];
        }
        __syncthreads();

        // phi: xw = x @ omega^T, ssq fused. 4 rows x 2 pairs per thread.
        float2 xw[4][2], ss2[4];
#pragma unroll
        for (int k = 0; k < 4; ++k) {
            ss2[k] = make_float2(0.f, 0.f);
            xw[k][0] = make_float2(0.f, 0.f);
            xw[k][1] = make_float2(0.f, 0.f);
        }
#pragma unroll 4
        for (int f = 0; f < FF; f += 2) {
            float2 xv[4];
#pragma unroll
            for (int k = 0; k < 4; ++k)
                xv[k] = *(const float2*)&x_s[(rg + 16 * k) * XP + f];
            const float2* om0 = (const float2*)&omega_s[f * MMF];
            const float2* om1 = (const float2*)&omega_s[(f + 1) * MMF];
            float2 o0[2], o1[2];
#pragma unroll
            for (int i = 0; i < 2; ++i) { o0[i] = om0[mg + 32 * i]; o1[i] = om1[mg + 32 * i]; }
#pragma unroll
            for (int k = 0; k < 4; ++k) {
                ss2[k] = ffma2(xv[k], xv[k], ss2[k]);
                float2 a0 = make_float2(xv[k].x, xv[k].x);
                float2 a1 = make_float2(xv[k].y, xv[k].y);
#pragma unroll
                for (int i = 0; i < 2; ++i) {
                    xw[k][i] = ffma2(a0, o0[i], xw[k][i]);
                    xw[k][i] = ffma2(a1, o1[i], xw[k][i]);
                }
            }
        }
#pragma unroll
        for (int k = 0; k < 4; ++k) {
            int r = rg + 16 * k;
            float sc = 0.5f * (ss2[k].x + ss2[k].y);
            float* kr = &kphi[r * KPP];
#pragma unroll
            for (int i = 0; i < 2; ++i) {
                int m = 2 * (mg + 32 * i);          // <= 126
                float w0 = xw[k][i].x, w1 = xw[k][i].y;
                *(float2*)&kr[m] = make_float2(
                    (__expf(w0 - sc) + EPSF) * SCALEF,
                    (__expf(w1 - sc) + EPSF) * SCALEF);
                *(float2*)&kr[m + MMF] = make_float2(   // <= 255 < KPP
                    (__expf(-w0 - sc) + EPSF) * SCALEF,
                    (__expf(-w1 - sc) + EPSF) * SCALEF);
            }
        }
        __syncthreads();

        // kv accumulate: 4 features x 8 cols per thread
#pragma unroll 2
        for (int r = 0; r < 64; ++r) {
            const float* kr = &kphi[r * KPP + 2 * fg];
            float2 k01 = *(const float2*)kr;
            float2 k23 = *(const float2*)(kr + MMF);
            const float2* vr = (const float2*)&v_s[r * VP + 8 * dgrp];
            float2 vv[4];
#pragma unroll
            for (int p = 0; p < 4; ++p) vv[p] = vr[p];
            float kk[4] = {k01.x, k01.y, k23.x, k23.y};
#pragma unroll
            for (int j = 0; j < 4; ++j) {
                float2 kj = make_float2(kk[j], kk[j]);
#pragma unroll
                for (int p = 0; p < 4; ++p) acc[j][p] = ffma2(kj, vv[p], acc[j][p]);
            }
            if (dgrp == 0) {
#pragma unroll
                for (int j = 0; j < 4; ++j) accn[j] += kk[j];
            }
        }
    }

    const size_t base = (size_t)(b * NCHUNK + chunk) * TWOM;
#pragma unroll
    for (int j = 0; j < 4; ++j) {
        int feat = 2 * fg + (j & 1) + (j >> 1) * MMF;   // <= 255
        float* dst = &g_part[(base + feat) * KVW];
#pragma unroll
        for (int p = 0; p < 4; ++p)
            *(float2*)&dst[8 * dgrp + 2 * p] = acc[j][p];
        if (dgrp == 0) dst[64] = accn[j];
    }
}

// ---------------------------------------------------------------------------
// Kernel 2: deterministic reduction of NCHUNK partials (float4 vectorized).
// ---------------------------------------------------------------------------
__global__ void reduce_kernel() {
    const int per_b4 = TWOM * KVW / 4;   // 4224 float4 per (b,chunk)
    int idx = blockIdx.x * blockDim.x + threadIdx.x;
    if (idx < BB * per_b4) {
        int b = idx / per_b4;
        int rem = idx - b * per_b4;
        const float4* src = (const float4*)g_part + (size_t)b * NCHUNK * per_b4 + rem;
        float4 s = make_float4(0.f, 0.f, 0.f, 0.f);
#pragma unroll
        for (int c = 0; c < NCHUNK; ++c) {
            float4 v = src[(size_t)c * per_b4];
            s.x += v.x; s.y += v.y; s.z += v.z; s.w += v.w;
        }
        ((float4*)g_kv)[idx] = s;
    }
}

// ---------------------------------------------------------------------------
// Kernel 3: block = (b, 128 t-rows). 256 threads.
// phi(query) transposed in SMEM (2 subpasses) -> qkv GEMM -> normalize.
// ---------------------------------------------------------------------------
__global__ __launch_bounds__(256, 1)
void qkv_kernel(const float* __restrict__ query,
                const float* __restrict__ omega,
                float* __restrict__ out) {
    extern __shared__ float sm[];
    float* qphiT   = sm;                         // [256][130] = 33280
    float* unionA  = sm + TWOM * 130;            // 16896 floats
    float* omega_s = unionA;                     // phase1: 8192
    float* x_s     = unionA + 8192;              // phase1: 64*XP = 4224
    float* kv_s    = unionA;                     // phase2: 256*KVW = 16896
    float* norm_s  = sm + TWOM * 130 + TWOM * KVW;  // 128

    const int tid = threadIdx.x;
    const int b = blockIdx.y;
    const int t0 = blockIdx.x * 128;

    for (int idx = tid; idx < MMF * FF; idx += 256) {
        int m = idx >> 6, f = idx & 63;
        omega_s[f * MMF + m] = omega[idx];
    }

    const int rg4 = tid & 15;       // phi rows rg4+16k (k<4)
    const int mg  = tid >> 4;       // phi pairs mg+16i (i<4) -> 64 pairs total

    for (int sp = 0; sp < 2; ++sp) {
        const int rbase = sp * 64;
        __syncthreads();  // omega load (sp0) / previous x_s readers (sp1)
        const float4* qp = (const float4*)(query + ((size_t)b * TT + t0 + rbase) * FF);
#pragma unroll
        for (int q = 0; q < 4; ++q) {
            int idx = tid + q * 256;
            int r = idx >> 4, c = (idx & 15) * 4;
            float4 xv = qp[idx];
            float* xd = &x_s[r * XP + c];
            *(float2*)xd       = make_float2(xv.x, xv.y);
            *(float2*)(xd + 2) = make_float2(xv.z, xv.w);
        }
        __syncthreads();

        float2 xw[4][4], ss2[4];
#pragma unroll
        for (int k = 0; k < 4; ++k) {
            ss2[k] = make_float2(0.f, 0.f);
#pragma unroll
            for (int i = 0; i < 4; ++i) xw[k][i] = make_float2(0.f, 0.f);
        }
#pragma unroll 4
        for (int f = 0; f < FF; f += 2) {
            float2 xv[4];
#pragma unroll
            for (int k = 0; k < 4; ++k)
                xv[k] = *(const float2*)&x_s[(rg4 + 16 * k) * XP + f];
            const float2* om0 = (const float2*)&omega_s[f * MMF];
            const float2* om1 = (const float2*)&omega_s[(f + 1) * MMF];
            float2 o0[4], o1[4];
#pragma unroll
            for (int i = 0; i < 4; ++i) { o0[i] = om0[mg + 16 * i]; o1[i] = om1[mg + 16 * i]; }
#pragma unroll
            for (int k = 0; k < 4; ++k) {
                ss2[k] = ffma2(xv[k], xv[k], ss2[k]);
                float2 a0 = make_float2(xv[k].x, xv[k].x);
                float2 a1 = make_float2(xv[k].y, xv[k].y);
#pragma unroll
                for (int i = 0; i < 4; ++i) {
                    xw[k][i] = ffma2(a0, o0[i], xw[k][i]);
                    xw[k][i] = ffma2(a1, o1[i], xw[k][i]);
                }
            }
        }
#pragma unroll
        for (int k = 0; k < 4; ++k) {
            int r = rbase + rg4 + 16 * k;
            float sc = 0.5f * (ss2[k].x + ss2[k].y);
#pragma unroll
            for (int i = 0; i < 4; ++i) {
                int m = 2 * (mg + 16 * i);           // <= 126
                float w0 = xw[k][i].x, w1 = xw[k][i].y;
                qphiT[m * 130 + r]             = (__expf(w0 - sc) + EPSF) * SCALEF;
                qphiT[(m + 1) * 130 + r]       = (__expf(w1 - sc) + EPSF) * SCALEF;
                qphiT[(m + MMF) * 130 + r]     = (__expf(-w0 - sc) + EPSF) * SCALEF;
                qphiT[(m + MMF + 1) * 130 + r] = (__expf(-w1 - sc) + EPSF) * SCALEF;
            }
        }
    }
    __syncthreads();

    // load kv (overwrites omega/x region)
    {
        const float4* src = (const float4*)&g_kv[(size_t)b * TWOM * KVW];
#pragma unroll
        for (int q = 0; q < 17; ++q) {
            int idx = tid + q * 256;
            if (idx < TWOM * KVW / 4) ((float4*)kv_s)[idx] = src[idx];
        }
    }
    __syncthreads();

    // qkv GEMM: thread = rows {2rg, 2rg+1} x cols {16cg..16cg+15}
    const int rg = tid & 63;
    const int cg = tid >> 6;
    float2 a0[8], a1[8];
#pragma unroll
    for (int p = 0; p < 8; ++p) { a0[p] = make_float2(0.f, 0.f); a1[p] = make_float2(0.f, 0.f); }
    float n0 = 0.f, n1 = 0.f;

#pragma unroll 4
    for (int m = 0; m < TWOM; ++m) {
        float2 qv = *(const float2*)&qphiT[m * 130 + 2 * rg];
        const float2* kr = (const float2*)&kv_s[m * KVW + 16 * cg];
        float2 kvv[8];
#pragma unroll
        for (int p = 0; p < 8; ++p) kvv[p] = kr[p];
        float2 q0 = make_float2(qv.x, qv.x);
        float2 q1 = make_float2(qv.y, qv.y);
#pragma unroll
        for (int p = 0; p < 8; ++p) {
            a0[p] = ffma2(q0, kvv[p], a0[p]);
            a1[p] = ffma2(q1, kvv[p], a1[p]);
        }
        if (cg == 0) {
            float kn = kv_s[m * KVW + 64];
            n0 = fmaf(qv.x, kn, n0);
            n1 = fmaf(qv.y, kn, n1);
        }
    }
    if (cg == 0) { norm_s[2 * rg] = n0; norm_s[2 * rg + 1] = n1; }
    __syncthreads();

    float i0 = 1.0f / norm_s[2 * rg];
    float i1 = 1.0f / norm_s[2 * rg + 1];
    float* o = out + ((size_t)b * TT + t0 + 2 * rg) * DD + 16 * cg;
#pragma unroll
    for (int p = 0; p < 8; ++p)
        *(float2*)&o[2 * p] = make_float2(a0[p].x * i0, a0[p].y * i0);
#pragma unroll
    for (int p = 0; p < 8; ++p)
        *(float2*)&o[DD + 2 * p] = make_float2(a1[p].x * i1, a1[p].y * i1);
}

// ---------------------------------------------------------------------------

#define KV_SMEM  ((8192 + 64*XP + 64*VP + 64*KPP) * 4)
#define QKV_SMEM ((TWOM*130 + TWOM*KVW + 128) * 4)

extern "C" void kernel_launch(void* const* d_in, const int* in_sizes, int n_in,
                              void* d_out, int out_size) {
    const float* query = (const float*)d_in[0];
    const float* value = (const float*)d_in[1];
    const float* key   = (const float*)d_in[2];
    const float* omega = (const float*)d_in[3];
    float* out = (float*)d_out;

    cudaFuncSetAttribute(kv_kernel, cudaFuncAttributeMaxDynamicSharedMemorySize, KV_SMEM);
    cudaFuncSetAttribute(qkv_kernel, cudaFuncAttributeMaxDynamicSharedMemorySize, QKV_SMEM);

    kv_kernel<<<dim3(NCHUNK, BB), 512, KV_SMEM>>>(key, value, omega);
    reduce_kernel<<<(BB * TWOM * KVW / 4 + 255) / 256, 256>>>();
    qkv_kernel<<<dim3(TT / 128, BB), 256, QKV_SMEM>>>(query, omega, out);
}